// round 10
// baseline (speedup 1.0000x reference)
#include <cuda_runtime.h>
#include <cuda_bf16.h>
#include <cmath>

// Fractional LIF SNN — frozen numeric contract (validated R5-R9, rel_err 2e-6):
//   * w_sh via f32 powf (libdevice __nv_powf, matches XLA-GPU)
//   * I_h: per-output single f32 accumulator, fmaf chain, k strictly ascending
//     (fma.rn.f32x2: each 64-bit lane is exactly that chain)
//   * mem sums: ascending-s f32 fmaf chains (hidden AND output)
//   * I_o: exact sum of selected f32 weights (spk in {0,1}), rounded once
//   * elementwise recurrence ops in reference f32 order
// R10 GEMM: tile 64(m) x 128(n) x 16(k), grid 256, duplicated-A smem so the
// packed {a,a} FFMA2 operand comes straight from LDS.128 (no pack2 MOVs).
// Issue mix/k/thread: 2 LDS.128 + 4 LDS.64 + 16 FFMA2 -> fma cap 0.727.

#define B_DIM   64
#define T_DIM   64
#define NIN     784
#define NHID    512
#define NOUT    10

__device__ float    g_I[B_DIM * T_DIM * NHID];    // 8 MB hidden currents
__device__ unsigned g_spk[B_DIM * T_DIM * 16];    // 256 KB spike bitmasks

// ---------------------------------------------------------------------------
__device__ __forceinline__ unsigned long long ffma2(unsigned long long a,
                                                    unsigned long long b,
                                                    unsigned long long c) {
    unsigned long long d;
    asm("fma.rn.f32x2 %0, %1, %2, %3;" : "=l"(d) : "l"(a), "l"(b), "l"(c));
    return d;
}

// ---------------------------------------------------------------------------
// GEMM: C[m, n] = seqchain_k( A[m,k]*W[n,k] ) + bias[n]
// M = 4096, K = 784, N = 512.  Tile 64x128x16, 256 threads, 4m x 8n per
// thread (4 packed f32x2 per m), grid (64, 4) = 256 blocks.
// As stores each a twice ({a,a} pairs) -> FFMA2 a-operand via direct LDS.
// Bit-identical to the scalar ascending-k chain.
// ---------------------------------------------------------------------------
#define BM 64
#define BN 128
#define BK 16
#define ASTRIDE (2 * BM + 8)    // 136 floats, 16B-aligned rows
#define WSTRIDE (BN + 4)        // 132 floats

__global__ void __launch_bounds__(256, 3)
snn_gemm(const float* __restrict__ A, const float* __restrict__ W,
         const float* __restrict__ bias, float* __restrict__ C) {
    __shared__ float As[2][BK][ASTRIDE];   // duplicated: [k][2m]=[k][2m+1]=a
    __shared__ float Ws[2][BK][WSTRIDE];

    const int tid = threadIdx.x;
    const int tx  = tid & 15;        // n-group (8 n as 4 pairs: 2tx+32j)
    const int ty  = tid >> 4;        // m-group (4 m: ty*4)
    const int m_blk = blockIdx.x * BM;
    const int n_blk = blockIdx.y * BN;

    // A loader: 64 rows x 16 k / 256 thr = 4 floats each
    const int arow = tid >> 2;           // 0..63
    const int akq  = (tid & 3) * 4;      // 0,4,8,12
    // W loader: 128 rows x 16 k / 256 thr = 8 floats each
    const int wrow = tid >> 1;           // 0..127
    const int wkq  = (tid & 1) * 8;      // 0 or 8

    const float* Ap = A + (size_t)(m_blk + arow) * NIN + akq;
    const float* Wp = W + (size_t)(n_blk + wrow) * NIN + wkq;

    float4 ra, rw0, rw1;

    // prologue: tile 0
    ra  = *(const float4*)(Ap);
    rw0 = *(const float4*)(Wp);
    rw1 = *(const float4*)(Wp + 4);
    {
        As[0][akq + 0][2 * arow] = ra.x; As[0][akq + 0][2 * arow + 1] = ra.x;
        As[0][akq + 1][2 * arow] = ra.y; As[0][akq + 1][2 * arow + 1] = ra.y;
        As[0][akq + 2][2 * arow] = ra.z; As[0][akq + 2][2 * arow + 1] = ra.z;
        As[0][akq + 3][2 * arow] = ra.w; As[0][akq + 3][2 * arow + 1] = ra.w;
        Ws[0][wkq + 0][wrow] = rw0.x; Ws[0][wkq + 1][wrow] = rw0.y;
        Ws[0][wkq + 2][wrow] = rw0.z; Ws[0][wkq + 3][wrow] = rw0.w;
        Ws[0][wkq + 4][wrow] = rw1.x; Ws[0][wkq + 5][wrow] = rw1.y;
        Ws[0][wkq + 6][wrow] = rw1.z; Ws[0][wkq + 7][wrow] = rw1.w;
    }
    __syncthreads();

    unsigned long long acc[4][4];
#pragma unroll
    for (int m = 0; m < 4; m++)
#pragma unroll
        for (int j = 0; j < 4; j++) acc[m][j] = 0ULL;

    const int NKT = NIN / BK;   // 49
    for (int kt = 0; kt < NKT; kt++) {
        const int cur = kt & 1;
        if (kt < NKT - 1) {
            const float* Ap2 = Ap + (kt + 1) * BK;
            const float* Wp2 = Wp + (kt + 1) * BK;
            ra  = *(const float4*)(Ap2);
            rw0 = *(const float4*)(Wp2);
            rw1 = *(const float4*)(Wp2 + 4);
        }
#pragma unroll
        for (int k = 0; k < BK; k++) {
            // {a,a} pairs for m0..m0+3 via two LDS.128 (2 pairs each)
            const float4 ap0 = *(const float4*)&As[cur][k][8 * ty];
            const float4 ap1 = *(const float4*)&As[cur][k][8 * ty + 4];
            const unsigned long long a0 = ((const unsigned long long*)&ap0)[0];
            const unsigned long long a1 = ((const unsigned long long*)&ap0)[1];
            const unsigned long long a2 = ((const unsigned long long*)&ap1)[0];
            const unsigned long long a3 = ((const unsigned long long*)&ap1)[1];
            unsigned long long b2[4];
#pragma unroll
            for (int j = 0; j < 4; j++)
                b2[j] = *(const unsigned long long*)&Ws[cur][k][2 * tx + 32 * j];
#pragma unroll
            for (int j = 0; j < 4; j++) {
                acc[0][j] = ffma2(a0, b2[j], acc[0][j]);
                acc[1][j] = ffma2(a1, b2[j], acc[1][j]);
                acc[2][j] = ffma2(a2, b2[j], acc[2][j]);
                acc[3][j] = ffma2(a3, b2[j], acc[3][j]);
            }
        }
        if (kt < NKT - 1) {
            const int nxt = cur ^ 1;
            As[nxt][akq + 0][2 * arow] = ra.x; As[nxt][akq + 0][2 * arow + 1] = ra.x;
            As[nxt][akq + 1][2 * arow] = ra.y; As[nxt][akq + 1][2 * arow + 1] = ra.y;
            As[nxt][akq + 2][2 * arow] = ra.z; As[nxt][akq + 2][2 * arow + 1] = ra.z;
            As[nxt][akq + 3][2 * arow] = ra.w; As[nxt][akq + 3][2 * arow + 1] = ra.w;
            Ws[nxt][wkq + 0][wrow] = rw0.x; Ws[nxt][wkq + 1][wrow] = rw0.y;
            Ws[nxt][wkq + 2][wrow] = rw0.z; Ws[nxt][wkq + 3][wrow] = rw0.w;
            Ws[nxt][wkq + 4][wrow] = rw1.x; Ws[nxt][wkq + 5][wrow] = rw1.y;
            Ws[nxt][wkq + 6][wrow] = rw1.z; Ws[nxt][wkq + 7][wrow] = rw1.w;
            __syncthreads();
        }
    }

    // epilogue: add bias, store float2 (lo -> col, hi -> col+1)
#pragma unroll
    for (int m = 0; m < 4; m++) {
        const int gm = m_blk + ty * 4 + m;
#pragma unroll
        for (int j = 0; j < 4; j++) {
            const int col = n_blk + 2 * tx + 32 * j;
            const unsigned long long v = acc[m][j];
            const float lo = __uint_as_float((unsigned)(v & 0xffffffffu));
            const float hi = __uint_as_float((unsigned)(v >> 32));
            float2 o;
            o.x = __fadd_rn(lo, bias[col]);
            o.y = __fadd_rn(hi, bias[col + 1]);
            *(float2*)&C[(size_t)gm * NHID + col] = o;
        }
    }
}

// ---------------------------------------------------------------------------
// Hidden recurrence: 128 blocks (2 per batch item) x 256 threads, no barriers
// in the time loop. Spikes exported as ballot bitmasks to g_spk.
// ---------------------------------------------------------------------------
__global__ void __launch_bounds__(256, 1)
snn_hidden(float scale) {
    const int b    = blockIdx.x >> 1;
    const int half = blockIdx.x & 1;
    const int tid  = threadIdx.x;
    const int lane = tid & 31;
    const int wid  = tid >> 5;
    const int h    = half * 256 + tid;

    __shared__ float w_sh[T_DIM];
    if (tid < T_DIM) {
        // f32 powf == libdevice __nv_powf == XLA-GPU lowering (verified exact)
        const float lagf = (float)tid;
        w_sh[tid] = (tid >= 2)
                        ? (powf(lagf, 0.8f) - powf(lagf - 1.0f, 0.8f))
                        : 0.0f;
    }
    __syncthreads();

    float D[T_DIM];
    float V = 0.0f;   // VRESET
    const float* Ibase = g_I + (size_t)(b * T_DIM) * NHID + h;
    float Ibuf[4];
    Ibuf[0] = Ibase[0];
    Ibuf[1] = Ibase[NHID];
    Ibuf[2] = Ibase[2 * NHID];
    Ibuf[3] = Ibase[3 * NHID];
    const float GLc = 0.025f;

#pragma unroll
    for (int t = 0; t < T_DIM; t++) {
        const float Icur = Ibuf[t & 3];
        if (t + 4 < T_DIM)
            Ibuf[t & 3] = Ibase[(size_t)(t + 4) * NHID];

        // hidden memory: f32 sequential fmaf chain, s ascending (frozen)
        float mem = 0.0f;
#pragma unroll
        for (int s = 0; s <= t - 2; s++)
            mem = fmaf(w_sh[t - s], D[s], mem);

        // Caputo L1 update, f32 ops in reference order
        const float f  = __fadd_rn(__fmul_rn(-GLc, V), Icur);
        const float g  = __fmul_rn(scale, f);
        const float h2 = __fmul_rn(g, 2.0f);
        const float Vn = __fsub_rn(__fadd_rn(V, h2), mem);
        const float Vp = (Vn > 1.0f) ? 0.0f : Vn;
        D[t] = __fsub_rn(Vp, V);
        V = Vp;

        const unsigned msk = __ballot_sync(0xffffffffu, Vn > 1.0f);
        if (lane == 0)
            g_spk[(b * T_DIM + t) * 16 + half * 8 + wid] = msk;
    }
}

// ---------------------------------------------------------------------------
// Output layer: 64 blocks (per batch item) x 512 threads.
//   phase 2: I_o via int64 fixed-point exact sums of selected W_o entries.
//   phase 3: output recurrence on 10 threads (frozen f32 chains).
// ---------------------------------------------------------------------------
#define FIX  9007199254740992.0   // 2^53

__global__ void __launch_bounds__(512, 1)
snn_out(const float* __restrict__ Wo, const float* __restrict__ bo,
        float* __restrict__ out, float scale) {
    const int b    = blockIdx.x;
    const int tid  = threadIdx.x;
    const int lane = tid & 31;
    const int wid  = tid >> 5;

    __shared__ float     w_sh[T_DIM];
    __shared__ unsigned  msk_sh[T_DIM][16];       // 4 KB
    __shared__ long long Wo_i[NOUT][NHID];        // 40 KB
    __shared__ float     Io_sh[T_DIM][NOUT];      // 2.5 KB

    if (tid < T_DIM) {
        const float lagf = (float)tid;
        w_sh[tid] = (tid >= 2)
                        ? (powf(lagf, 0.8f) - powf(lagf - 1.0f, 0.8f))
                        : 0.0f;
    }
    for (int i = tid; i < T_DIM * 16; i += 512)
        msk_sh[i >> 4][i & 15] = g_spk[b * T_DIM * 16 + i];
    for (int i = tid; i < NOUT * NHID; i += 512)
        Wo_i[i / NHID][i % NHID] = (long long)((double)Wo[i] * FIX);
    __syncthreads();

    // ---- phase 2: 640 selective sums; warp w handles t = 4w .. 4w+3 -------
    {
        const unsigned bit = 1u << lane;
        const int t0 = wid * 4;
#pragma unroll
        for (int tt = 0; tt < 4; tt++) {
            const int t = t0 + tt;
            unsigned m[16];
#pragma unroll
            for (int j = 0; j < 16; j++) m[j] = msk_sh[t][j];
            for (int o = 0; o < NOUT; o++) {
                long long s = 0;
#pragma unroll
                for (int j = 0; j < 16; j++)
                    if (m[j] & bit) s += Wo_i[o][j * 32 + lane];
#pragma unroll
                for (int off = 16; off > 0; off >>= 1)
                    s += __shfl_xor_sync(0xffffffffu, s, off);
                if (lane == 0)
                    Io_sh[t][o] =
                        __fadd_rn((float)((double)s * (1.0 / FIX)), bo[o]);
            }
        }
    }
    __syncthreads();

    // ---- phase 3: output recurrence (10 threads) --------------------------
    if (tid < NOUT) {
        const int o = tid;
        float Do[T_DIM];
        float Vo = 0.0f;
        const float GLc = 0.025f;

#pragma unroll
        for (int t = 0; t < T_DIM; t++) {
            // output memory: f32 sequential fmaf chain, s ascending (frozen)
            float mo = 0.0f;
#pragma unroll
            for (int s = 0; s <= t - 2; s++)
                mo = fmaf(w_sh[t - s], Do[s], mo);

            const float Io  = Io_sh[t][o];
            const float fo  = __fadd_rn(__fmul_rn(-GLc, Vo), Io);
            const float go  = __fmul_rn(scale, fo);
            const float ho  = __fmul_rn(go, 2.0f);
            const float Von = __fsub_rn(__fadd_rn(Vo, ho), mo);
            const float spko = (Von > 1.0f) ? 1.0f : 0.0f;
            const float Vop  = (Von > 1.0f) ? 0.0f : Von;
            Do[t] = __fsub_rn(Vop, Vo);
            Vo = Vop;

            const int idx = (t * B_DIM + b) * NOUT + o;
            out[idx] = spko;                               // spk_trace [T,B,O]
            out[T_DIM * B_DIM * NOUT + idx] = Vo;          // mem_trace [T,B,O]
        }
    }
}

// ---------------------------------------------------------------------------
extern "C" void kernel_launch(void* const* d_in, const int* in_sizes, int n_in,
                              void* d_out, int out_size) {
    const float* data = (const float*)d_in[0];   // [B,T,NIN]
    const float* W_h  = (const float*)d_in[1];   // [NHID,NIN]
    const float* b_h  = (const float*)d_in[2];   // [NHID]
    const float* W_o  = (const float*)d_in[3];   // [NOUT,NHID]
    const float* b_o  = (const float*)d_in[4];   // [NOUT]
    // d_in[5] = plotting (unused)

    float* I_ptr = nullptr;
    cudaGetSymbolAddress((void**)&I_ptr, g_I);   // no alloc; capture-safe

    const float scale = (float)(pow(0.1, 0.2) * tgamma(1.8));

    dim3 ggrid(B_DIM * T_DIM / BM, NHID / BN);   // (64, 4) = 256 blocks
    snn_gemm<<<ggrid, 256>>>(data, W_h, b_h, I_ptr);
    snn_hidden<<<2 * B_DIM, 256>>>(scale);
    snn_out<<<B_DIM, 512>>>(W_o, b_o, (float*)d_out, scale);
}

// round 13
// speedup vs baseline: 1.2182x; 1.2182x over previous
#include <cuda_runtime.h>
#include <cuda_bf16.h>
#include <cmath>

// Fractional LIF SNN — frozen numeric contract (validated R5-R10, rel_err 2e-6):
//   * w_sh via f32 powf (libdevice __nv_powf, matches XLA-GPU)
//   * I_h: per-output single f32 accumulator, fmaf chain, k strictly ascending
//     (fma.rn.f32x2: each 64-bit lane is exactly that chain)
//   * mem sums: ascending-s f32 fmaf chains (hidden AND output)
//   * I_o: exact sum of selected f32 weights (spk in {0,1}), rounded once
//   * elementwise recurrence ops in reference f32 order
// R13 GEMM = R11 design with DYNAMIC shared memory (50 KB > 48 KB static cap):
// tile 128x128x16, grid 128, 8x8/thread, accumulator pairs along M so the
// {A[m],A[m+1]} FFMA2 operand comes natively from LDS.128 (no pack2 MOVs);
// B duplicated in smem so {b,b} comes from LDS.128 (2 dup-pairs per load).
// Issue mix/k/thread: 2+4 LDS.128 + 32 FFMA2 = 38 slots -> fma cap 0.84.

#define B_DIM   64
#define T_DIM   64
#define NIN     784
#define NHID    512
#define NOUT    10

__device__ float    g_I[B_DIM * T_DIM * NHID];    // 8 MB hidden currents
__device__ unsigned g_spk[B_DIM * T_DIM * 16];    // 256 KB spike bitmasks

// ---------------------------------------------------------------------------
__device__ __forceinline__ unsigned long long ffma2(unsigned long long a,
                                                    unsigned long long b,
                                                    unsigned long long c) {
    unsigned long long d;
    asm("fma.rn.f32x2 %0, %1, %2, %3;" : "=l"(d) : "l"(a), "l"(b), "l"(c));
    return d;
}

// ---------------------------------------------------------------------------
// GEMM: C[m, n] = seqchain_k( A[m,k]*W[n,k] ) + bias[n]
// M = 4096, K = 784, N = 512.  Tile 128x128x16, 256 threads, 8m x 8n per
// thread; accumulators are M-pairs: acc = {C[m][n], C[m+1][n]}.
// As: natural [k][m] layout (LDS.128 -> 2 m-pairs).
// Wsd: duplicated [k][2n]=[k][2n+1]=W[n] (LDS.128 -> 2 {b,b} pairs).
// Dynamic smem: As 2*16*132 + Wsd 2*16*260 floats = 50176 bytes.
// Bit-identical to the scalar ascending-k chain.
// ---------------------------------------------------------------------------
#define BM 128
#define BN 128
#define BK 16
#define ASTRIDE (BM + 4)        // 132 floats (16B-aligned rows)
#define WSTRIDE (2 * BN + 4)    // 260 floats (16B-aligned rows)
#define GEMM_SMEM_BYTES ((2 * BK * ASTRIDE + 2 * BK * WSTRIDE) * 4)

__global__ void __launch_bounds__(256, 1)
snn_gemm(const float* __restrict__ A, const float* __restrict__ W,
         const float* __restrict__ bias, float* __restrict__ C) {
    extern __shared__ float smem[];
    float (*As)[BK][ASTRIDE]  = (float (*)[BK][ASTRIDE])smem;
    float (*Wsd)[BK][WSTRIDE] = (float (*)[BK][WSTRIDE])(smem + 2 * BK * ASTRIDE);

    const int tid = threadIdx.x;
    const int tx  = tid & 15;        // n-group: n = 2tx + h + 32jj
    const int ty  = tid >> 4;        // m-group: m = 8ty .. 8ty+7
    const int m_blk = blockIdx.x * BM;
    const int n_blk = blockIdx.y * BN;

    const int row = tid >> 2;            // 0..63
    const int kq4 = (tid & 3) * 4;       // 0,4,8,12

    const float* Ap = A + (size_t)(m_blk + row) * NIN + kq4;
    const float* Wp = W + (size_t)(n_blk + row) * NIN + kq4;

    float4 ra0, ra1, rw0, rw1;

    // prologue: tile 0
    ra0 = *(const float4*)(Ap);
    ra1 = *(const float4*)(Ap + 64 * NIN);
    rw0 = *(const float4*)(Wp);
    rw1 = *(const float4*)(Wp + 64 * NIN);
    {
        As[0][kq4 + 0][row] = ra0.x; As[0][kq4 + 1][row] = ra0.y;
        As[0][kq4 + 2][row] = ra0.z; As[0][kq4 + 3][row] = ra0.w;
        As[0][kq4 + 0][row + 64] = ra1.x; As[0][kq4 + 1][row + 64] = ra1.y;
        As[0][kq4 + 2][row + 64] = ra1.z; As[0][kq4 + 3][row + 64] = ra1.w;
        const float w0[4] = {rw0.x, rw0.y, rw0.z, rw0.w};
        const float w1[4] = {rw1.x, rw1.y, rw1.z, rw1.w};
#pragma unroll
        for (int i = 0; i < 4; i++) {
            *(float2*)&Wsd[0][kq4 + i][2 * row] = make_float2(w0[i], w0[i]);
            *(float2*)&Wsd[0][kq4 + i][2 * (row + 64)] = make_float2(w1[i], w1[i]);
        }
    }
    __syncthreads();

    unsigned long long acc[4][8];   // [m-pair][n]
#pragma unroll
    for (int mp = 0; mp < 4; mp++)
#pragma unroll
        for (int j = 0; j < 8; j++) acc[mp][j] = 0ULL;

    const int NKT = NIN / BK;   // 49
    for (int kt = 0; kt < NKT; kt++) {
        const int cur = kt & 1;
        if (kt < NKT - 1) {
            const float* Ap2 = Ap + (kt + 1) * BK;
            const float* Wp2 = Wp + (kt + 1) * BK;
            ra0 = *(const float4*)(Ap2);
            ra1 = *(const float4*)(Ap2 + 64 * NIN);
            rw0 = *(const float4*)(Wp2);
            rw1 = *(const float4*)(Wp2 + 64 * NIN);
        }
#pragma unroll
        for (int k = 0; k < BK; k++) {
            // 4 m-pairs from two LDS.128 (natural As layout)
            const float4 ap0 = *(const float4*)&As[cur][k][8 * ty];
            const float4 ap1 = *(const float4*)&As[cur][k][8 * ty + 4];
            const unsigned long long a0 = ((const unsigned long long*)&ap0)[0];
            const unsigned long long a1 = ((const unsigned long long*)&ap0)[1];
            const unsigned long long a2 = ((const unsigned long long*)&ap1)[0];
            const unsigned long long a3 = ((const unsigned long long*)&ap1)[1];
            // 8 duplicated {b,b} pairs from four LDS.128
#pragma unroll
            for (int jj = 0; jj < 4; jj++) {
                const float4 bv = *(const float4*)&Wsd[cur][k][4 * tx + 64 * jj];
                const unsigned long long bd0 = ((const unsigned long long*)&bv)[0];
                const unsigned long long bd1 = ((const unsigned long long*)&bv)[1];
                acc[0][2 * jj]     = ffma2(a0, bd0, acc[0][2 * jj]);
                acc[1][2 * jj]     = ffma2(a1, bd0, acc[1][2 * jj]);
                acc[2][2 * jj]     = ffma2(a2, bd0, acc[2][2 * jj]);
                acc[3][2 * jj]     = ffma2(a3, bd0, acc[3][2 * jj]);
                acc[0][2 * jj + 1] = ffma2(a0, bd1, acc[0][2 * jj + 1]);
                acc[1][2 * jj + 1] = ffma2(a1, bd1, acc[1][2 * jj + 1]);
                acc[2][2 * jj + 1] = ffma2(a2, bd1, acc[2][2 * jj + 1]);
                acc[3][2 * jj + 1] = ffma2(a3, bd1, acc[3][2 * jj + 1]);
            }
        }
        if (kt < NKT - 1) {
            const int nxt = cur ^ 1;
            As[nxt][kq4 + 0][row] = ra0.x; As[nxt][kq4 + 1][row] = ra0.y;
            As[nxt][kq4 + 2][row] = ra0.z; As[nxt][kq4 + 3][row] = ra0.w;
            As[nxt][kq4 + 0][row + 64] = ra1.x; As[nxt][kq4 + 1][row + 64] = ra1.y;
            As[nxt][kq4 + 2][row + 64] = ra1.z; As[nxt][kq4 + 3][row + 64] = ra1.w;
            const float w0[4] = {rw0.x, rw0.y, rw0.z, rw0.w};
            const float w1[4] = {rw1.x, rw1.y, rw1.z, rw1.w};
#pragma unroll
            for (int i = 0; i < 4; i++) {
                *(float2*)&Wsd[nxt][kq4 + i][2 * row] = make_float2(w0[i], w0[i]);
                *(float2*)&Wsd[nxt][kq4 + i][2 * (row + 64)] = make_float2(w1[i], w1[i]);
            }
            __syncthreads();
        }
    }

    // epilogue: add bias, store (lo -> row m, hi -> row m+1)
#pragma unroll
    for (int mp = 0; mp < 4; mp++) {
        const int gm = m_blk + ty * 8 + 2 * mp;
#pragma unroll
        for (int j = 0; j < 8; j++) {
            const int col = n_blk + 2 * tx + (j & 1) + 32 * (j >> 1);
            const unsigned long long v = acc[mp][j];
            const float lo = __uint_as_float((unsigned)(v & 0xffffffffu));
            const float hi = __uint_as_float((unsigned)(v >> 32));
            const float bz = bias[col];
            C[(size_t)gm * NHID + col]       = __fadd_rn(lo, bz);
            C[(size_t)(gm + 1) * NHID + col] = __fadd_rn(hi, bz);
        }
    }
}

// ---------------------------------------------------------------------------
// Hidden recurrence: 128 blocks (2 per batch item) x 256 threads, no barriers
// in the time loop. Spikes exported as ballot bitmasks to g_spk.
// ---------------------------------------------------------------------------
__global__ void __launch_bounds__(256, 1)
snn_hidden(float scale) {
    const int b    = blockIdx.x >> 1;
    const int half = blockIdx.x & 1;
    const int tid  = threadIdx.x;
    const int lane = tid & 31;
    const int wid  = tid >> 5;
    const int h    = half * 256 + tid;

    __shared__ float w_sh[T_DIM];
    if (tid < T_DIM) {
        // f32 powf == libdevice __nv_powf == XLA-GPU lowering (verified exact)
        const float lagf = (float)tid;
        w_sh[tid] = (tid >= 2)
                        ? (powf(lagf, 0.8f) - powf(lagf - 1.0f, 0.8f))
                        : 0.0f;
    }
    __syncthreads();

    float D[T_DIM];
    float V = 0.0f;   // VRESET
    const float* Ibase = g_I + (size_t)(b * T_DIM) * NHID + h;
    float Ibuf[4];
    Ibuf[0] = Ibase[0];
    Ibuf[1] = Ibase[NHID];
    Ibuf[2] = Ibase[2 * NHID];
    Ibuf[3] = Ibase[3 * NHID];
    const float GLc = 0.025f;

#pragma unroll
    for (int t = 0; t < T_DIM; t++) {
        const float Icur = Ibuf[t & 3];
        if (t + 4 < T_DIM)
            Ibuf[t & 3] = Ibase[(size_t)(t + 4) * NHID];

        // hidden memory: f32 sequential fmaf chain, s ascending (frozen)
        float mem = 0.0f;
#pragma unroll
        for (int s = 0; s <= t - 2; s++)
            mem = fmaf(w_sh[t - s], D[s], mem);

        // Caputo L1 update, f32 ops in reference order
        const float f  = __fadd_rn(__fmul_rn(-GLc, V), Icur);
        const float g  = __fmul_rn(scale, f);
        const float h2 = __fmul_rn(g, 2.0f);
        const float Vn = __fsub_rn(__fadd_rn(V, h2), mem);
        const float Vp = (Vn > 1.0f) ? 0.0f : Vn;
        D[t] = __fsub_rn(Vp, V);
        V = Vp;

        const unsigned msk = __ballot_sync(0xffffffffu, Vn > 1.0f);
        if (lane == 0)
            g_spk[(b * T_DIM + t) * 16 + half * 8 + wid] = msk;
    }
}

// ---------------------------------------------------------------------------
// Output layer: 64 blocks (per batch item) x 512 threads.
//   phase 2: I_o via int64 fixed-point exact sums of selected W_o entries.
//   phase 3: output recurrence on 10 threads (frozen f32 chains).
// ---------------------------------------------------------------------------
#define FIX  9007199254740992.0   // 2^53

__global__ void __launch_bounds__(512, 1)
snn_out(const float* __restrict__ Wo, const float* __restrict__ bo,
        float* __restrict__ out, float scale) {
    const int b    = blockIdx.x;
    const int tid  = threadIdx.x;
    const int lane = tid & 31;
    const int wid  = tid >> 5;

    __shared__ float     w_sh[T_DIM];
    __shared__ unsigned  msk_sh[T_DIM][16];       // 4 KB
    __shared__ long long Wo_i[NOUT][NHID];        // 40 KB
    __shared__ float     Io_sh[T_DIM][NOUT];      // 2.5 KB

    if (tid < T_DIM) {
        const float lagf = (float)tid;
        w_sh[tid] = (tid >= 2)
                        ? (powf(lagf, 0.8f) - powf(lagf - 1.0f, 0.8f))
                        : 0.0f;
    }
    for (int i = tid; i < T_DIM * 16; i += 512)
        msk_sh[i >> 4][i & 15] = g_spk[b * T_DIM * 16 + i];
    for (int i = tid; i < NOUT * NHID; i += 512)
        Wo_i[i / NHID][i % NHID] = (long long)((double)Wo[i] * FIX);
    __syncthreads();

    // ---- phase 2: 640 selective sums; warp w handles t = 4w .. 4w+3 -------
    {
        const unsigned bit = 1u << lane;
        const int t0 = wid * 4;
#pragma unroll
        for (int tt = 0; tt < 4; tt++) {
            const int t = t0 + tt;
            unsigned m[16];
#pragma unroll
            for (int j = 0; j < 16; j++) m[j] = msk_sh[t][j];
            for (int o = 0; o < NOUT; o++) {
                long long s = 0;
#pragma unroll
                for (int j = 0; j < 16; j++)
                    if (m[j] & bit) s += Wo_i[o][j * 32 + lane];
#pragma unroll
                for (int off = 16; off > 0; off >>= 1)
                    s += __shfl_xor_sync(0xffffffffu, s, off);
                if (lane == 0)
                    Io_sh[t][o] =
                        __fadd_rn((float)((double)s * (1.0 / FIX)), bo[o]);
            }
        }
    }
    __syncthreads();

    // ---- phase 3: output recurrence (10 threads) --------------------------
    if (tid < NOUT) {
        const int o = tid;
        float Do[T_DIM];
        float Vo = 0.0f;
        const float GLc = 0.025f;

#pragma unroll
        for (int t = 0; t < T_DIM; t++) {
            // output memory: f32 sequential fmaf chain, s ascending (frozen)
            float mo = 0.0f;
#pragma unroll
            for (int s = 0; s <= t - 2; s++)
                mo = fmaf(w_sh[t - s], Do[s], mo);

            const float Io  = Io_sh[t][o];
            const float fo  = __fadd_rn(__fmul_rn(-GLc, Vo), Io);
            const float go  = __fmul_rn(scale, fo);
            const float ho  = __fmul_rn(go, 2.0f);
            const float Von = __fsub_rn(__fadd_rn(Vo, ho), mo);
            const float spko = (Von > 1.0f) ? 1.0f : 0.0f;
            const float Vop  = (Von > 1.0f) ? 0.0f : Von;
            Do[t] = __fsub_rn(Vop, Vo);
            Vo = Vop;

            const int idx = (t * B_DIM + b) * NOUT + o;
            out[idx] = spko;                               // spk_trace [T,B,O]
            out[T_DIM * B_DIM * NOUT + idx] = Vo;          // mem_trace [T,B,O]
        }
    }
}

// ---------------------------------------------------------------------------
extern "C" void kernel_launch(void* const* d_in, const int* in_sizes, int n_in,
                              void* d_out, int out_size) {
    const float* data = (const float*)d_in[0];   // [B,T,NIN]
    const float* W_h  = (const float*)d_in[1];   // [NHID,NIN]
    const float* b_h  = (const float*)d_in[2];   // [NHID]
    const float* W_o  = (const float*)d_in[3];   // [NOUT,NHID]
    const float* b_o  = (const float*)d_in[4];   // [NOUT]
    // d_in[5] = plotting (unused)

    float* I_ptr = nullptr;
    cudaGetSymbolAddress((void**)&I_ptr, g_I);   // no alloc; capture-safe

    // Opt in to >48KB dynamic smem (attribute set, not an allocation;
    // idempotent and capture-safe — not a stream operation).
    cudaFuncSetAttribute(snn_gemm,
                         cudaFuncAttributeMaxDynamicSharedMemorySize,
                         GEMM_SMEM_BYTES);

    const float scale = (float)(pow(0.1, 0.2) * tgamma(1.8));

    dim3 ggrid(B_DIM * T_DIM / BM, NHID / BN);   // (32, 4) = 128 blocks
    snn_gemm<<<ggrid, 256, GEMM_SMEM_BYTES>>>(data, W_h, b_h, I_ptr);
    snn_hidden<<<2 * B_DIM, 256>>>(scale);
    snn_out<<<B_DIM, 512>>>(W_o, b_o, (float*)d_out, scale);
}

// round 14
// speedup vs baseline: 1.2356x; 1.0143x over previous
#include <cuda_runtime.h>
#include <cuda_bf16.h>
#include <cmath>

// Fractional LIF SNN — frozen numeric contract (validated R5-R13, rel_err 2e-6):
//   * w_sh via f32 powf (libdevice __nv_powf, matches XLA-GPU)
//   * I_h: per-output single f32 accumulator, fmaf chain, k strictly ascending
//     (fma.rn.f32x2: each 64-bit lane is exactly that chain)
//   * mem sums: ascending-s f32 fmaf chains (hidden AND output)
//   * I_o: exact sum of selected f32 weights (spk in {0,1}), rounded once
//   * elementwise recurrence ops in reference f32 order
// R14 GEMM: R8 layout/mix (no smem duplication — both dup experiments lost on
// crossbar wavefronts) but 512 threads (4m x 8n per thread) -> 4 warps/SMSP
// at grid 128 to hide LDS latency and keep the FFMA2 pipe fed.

#define B_DIM   64
#define T_DIM   64
#define NIN     784
#define NHID    512
#define NOUT    10

__device__ float    g_I[B_DIM * T_DIM * NHID];    // 8 MB hidden currents
__device__ unsigned g_spk[B_DIM * T_DIM * 16];    // 256 KB spike bitmasks

// ---------------------------------------------------------------------------
__device__ __forceinline__ unsigned long long ffma2(unsigned long long a,
                                                    unsigned long long b,
                                                    unsigned long long c) {
    unsigned long long d;
    asm("fma.rn.f32x2 %0, %1, %2, %3;" : "=l"(d) : "l"(a), "l"(b), "l"(c));
    return d;
}
__device__ __forceinline__ unsigned long long pack2(float x) {
    unsigned long long d;
    asm("mov.b64 %0, {%1, %1};" : "=l"(d) : "f"(x));
    return d;
}

// ---------------------------------------------------------------------------
// GEMM: C[m, n] = seqchain_k( A[m,k]*W[n,k] ) + bias[n]
// M = 4096, K = 784, N = 512.  Tile 128x128x16, 512 threads, 4m x 8n per
// thread (8 n as 4 packed f32x2), double-buffered smem, grid (32,4)=128.
// Per warp per k: 1 LDS.128 (broadcast) + 4 LDS.64 + 4 pack2 + 16 FFMA2.
// Bit-identical to the scalar ascending-k chain.
// ---------------------------------------------------------------------------
#define BM 128
#define BN 128
#define BK 16
#define PAD 4

__global__ void __launch_bounds__(512, 1)
snn_gemm(const float* __restrict__ A, const float* __restrict__ W,
         const float* __restrict__ bias, float* __restrict__ C) {
    __shared__ float As[2][BK][BM + PAD];
    __shared__ float Ws[2][BK][BN + PAD];

    const int tid = threadIdx.x;
    const int tx  = tid & 15;        // n-group 0..15 (8 n: 2tx + 32j)
    const int ty  = tid >> 4;        // m-group 0..31 (4 m: ty*4)
    const int m_blk = blockIdx.x * BM;
    const int n_blk = blockIdx.y * BN;

    // loaders: one float4 per thread per matrix per tile
    const int row = tid >> 2;            // 0..127
    const int kq4 = (tid & 3) * 4;       // 0,4,8,12

    const float* Ap = A + (size_t)(m_blk + row) * NIN + kq4;
    const float* Wp = W + (size_t)(n_blk + row) * NIN + kq4;

    float4 ra, rw;

    // prologue: tile 0
    ra = *(const float4*)(Ap);
    rw = *(const float4*)(Wp);
    As[0][kq4 + 0][row] = ra.x; As[0][kq4 + 1][row] = ra.y;
    As[0][kq4 + 2][row] = ra.z; As[0][kq4 + 3][row] = ra.w;
    Ws[0][kq4 + 0][row] = rw.x; Ws[0][kq4 + 1][row] = rw.y;
    Ws[0][kq4 + 2][row] = rw.z; Ws[0][kq4 + 3][row] = rw.w;
    __syncthreads();

    unsigned long long acc[4][4];
#pragma unroll
    for (int m = 0; m < 4; m++)
#pragma unroll
        for (int j = 0; j < 4; j++) acc[m][j] = 0ULL;

    const int NKT = NIN / BK;   // 49
    for (int kt = 0; kt < NKT; kt++) {
        const int cur = kt & 1;
        if (kt < NKT - 1) {
            ra = *(const float4*)(Ap + (kt + 1) * BK);
            rw = *(const float4*)(Wp + (kt + 1) * BK);
        }
#pragma unroll
        for (int k = 0; k < BK; k++) {
            const float4 av = *(const float4*)&As[cur][k][ty * 4];
            unsigned long long b2[4];
#pragma unroll
            for (int j = 0; j < 4; j++)
                b2[j] = *(const unsigned long long*)&Ws[cur][k][2 * tx + 32 * j];
            const float avs[4] = {av.x, av.y, av.z, av.w};
#pragma unroll
            for (int m = 0; m < 4; m++) {
                const unsigned long long a2 = pack2(avs[m]);
#pragma unroll
                for (int j = 0; j < 4; j++)
                    acc[m][j] = ffma2(a2, b2[j], acc[m][j]);
            }
        }
        if (kt < NKT - 1) {
            const int nxt = cur ^ 1;
            As[nxt][kq4 + 0][row] = ra.x; As[nxt][kq4 + 1][row] = ra.y;
            As[nxt][kq4 + 2][row] = ra.z; As[nxt][kq4 + 3][row] = ra.w;
            Ws[nxt][kq4 + 0][row] = rw.x; Ws[nxt][kq4 + 1][row] = rw.y;
            Ws[nxt][kq4 + 2][row] = rw.z; Ws[nxt][kq4 + 3][row] = rw.w;
            __syncthreads();
        }
    }

    // epilogue: add bias, store float2 (lo -> col, hi -> col+1)
#pragma unroll
    for (int m = 0; m < 4; m++) {
        const int gm = m_blk + ty * 4 + m;
#pragma unroll
        for (int j = 0; j < 4; j++) {
            const int col = n_blk + 2 * tx + 32 * j;
            const unsigned long long v = acc[m][j];
            const float lo = __uint_as_float((unsigned)(v & 0xffffffffu));
            const float hi = __uint_as_float((unsigned)(v >> 32));
            float2 o;
            o.x = __fadd_rn(lo, bias[col]);
            o.y = __fadd_rn(hi, bias[col + 1]);
            *(float2*)&C[(size_t)gm * NHID + col] = o;
        }
    }
}

// ---------------------------------------------------------------------------
// Hidden recurrence: 128 blocks (2 per batch item) x 256 threads, no barriers
// in the time loop. Spikes exported as ballot bitmasks to g_spk.
// ---------------------------------------------------------------------------
__global__ void __launch_bounds__(256, 1)
snn_hidden(float scale) {
    const int b    = blockIdx.x >> 1;
    const int half = blockIdx.x & 1;
    const int tid  = threadIdx.x;
    const int lane = tid & 31;
    const int wid  = tid >> 5;
    const int h    = half * 256 + tid;

    __shared__ float w_sh[T_DIM];
    if (tid < T_DIM) {
        // f32 powf == libdevice __nv_powf == XLA-GPU lowering (verified exact)
        const float lagf = (float)tid;
        w_sh[tid] = (tid >= 2)
                        ? (powf(lagf, 0.8f) - powf(lagf - 1.0f, 0.8f))
                        : 0.0f;
    }
    __syncthreads();

    float D[T_DIM];
    float V = 0.0f;   // VRESET
    const float* Ibase = g_I + (size_t)(b * T_DIM) * NHID + h;
    float Ibuf[4];
    Ibuf[0] = Ibase[0];
    Ibuf[1] = Ibase[NHID];
    Ibuf[2] = Ibase[2 * NHID];
    Ibuf[3] = Ibase[3 * NHID];
    const float GLc = 0.025f;

#pragma unroll
    for (int t = 0; t < T_DIM; t++) {
        const float Icur = Ibuf[t & 3];
        if (t + 4 < T_DIM)
            Ibuf[t & 3] = Ibase[(size_t)(t + 4) * NHID];

        // hidden memory: f32 sequential fmaf chain, s ascending (frozen)
        float mem = 0.0f;
#pragma unroll
        for (int s = 0; s <= t - 2; s++)
            mem = fmaf(w_sh[t - s], D[s], mem);

        // Caputo L1 update, f32 ops in reference order
        const float f  = __fadd_rn(__fmul_rn(-GLc, V), Icur);
        const float g  = __fmul_rn(scale, f);
        const float h2 = __fmul_rn(g, 2.0f);
        const float Vn = __fsub_rn(__fadd_rn(V, h2), mem);
        const float Vp = (Vn > 1.0f) ? 0.0f : Vn;
        D[t] = __fsub_rn(Vp, V);
        V = Vp;

        const unsigned msk = __ballot_sync(0xffffffffu, Vn > 1.0f);
        if (lane == 0)
            g_spk[(b * T_DIM + t) * 16 + half * 8 + wid] = msk;
    }
}

// ---------------------------------------------------------------------------
// Output layer: 64 blocks (per batch item) x 512 threads.
//   phase 2: I_o via int64 fixed-point exact sums of selected W_o entries.
//   phase 3: output recurrence on 10 threads (frozen f32 chains).
// ---------------------------------------------------------------------------
#define FIX  9007199254740992.0   // 2^53

__global__ void __launch_bounds__(512, 1)
snn_out(const float* __restrict__ Wo, const float* __restrict__ bo,
        float* __restrict__ out, float scale) {
    const int b    = blockIdx.x;
    const int tid  = threadIdx.x;
    const int lane = tid & 31;
    const int wid  = tid >> 5;

    __shared__ float     w_sh[T_DIM];
    __shared__ unsigned  msk_sh[T_DIM][16];       // 4 KB
    __shared__ long long Wo_i[NOUT][NHID];        // 40 KB
    __shared__ float     Io_sh[T_DIM][NOUT];      // 2.5 KB

    if (tid < T_DIM) {
        const float lagf = (float)tid;
        w_sh[tid] = (tid >= 2)
                        ? (powf(lagf, 0.8f) - powf(lagf - 1.0f, 0.8f))
                        : 0.0f;
    }
    for (int i = tid; i < T_DIM * 16; i += 512)
        msk_sh[i >> 4][i & 15] = g_spk[b * T_DIM * 16 + i];
    for (int i = tid; i < NOUT * NHID; i += 512)
        Wo_i[i / NHID][i % NHID] = (long long)((double)Wo[i] * FIX);
    __syncthreads();

    // ---- phase 2: 640 selective sums; warp w handles t = 4w .. 4w+3 -------
    {
        const unsigned bit = 1u << lane;
        const int t0 = wid * 4;
#pragma unroll
        for (int tt = 0; tt < 4; tt++) {
            const int t = t0 + tt;
            unsigned m[16];
#pragma unroll
            for (int j = 0; j < 16; j++) m[j] = msk_sh[t][j];
            for (int o = 0; o < NOUT; o++) {
                long long s = 0;
#pragma unroll
                for (int j = 0; j < 16; j++)
                    if (m[j] & bit) s += Wo_i[o][j * 32 + lane];
#pragma unroll
                for (int off = 16; off > 0; off >>= 1)
                    s += __shfl_xor_sync(0xffffffffu, s, off);
                if (lane == 0)
                    Io_sh[t][o] =
                        __fadd_rn((float)((double)s * (1.0 / FIX)), bo[o]);
            }
        }
    }
    __syncthreads();

    // ---- phase 3: output recurrence (10 threads) --------------------------
    if (tid < NOUT) {
        const int o = tid;
        float Do[T_DIM];
        float Vo = 0.0f;
        const float GLc = 0.025f;

#pragma unroll
        for (int t = 0; t < T_DIM; t++) {
            // output memory: f32 sequential fmaf chain, s ascending (frozen)
            float mo = 0.0f;
#pragma unroll
            for (int s = 0; s <= t - 2; s++)
                mo = fmaf(w_sh[t - s], Do[s], mo);

            const float Io  = Io_sh[t][o];
            const float fo  = __fadd_rn(__fmul_rn(-GLc, Vo), Io);
            const float go  = __fmul_rn(scale, fo);
            const float ho  = __fmul_rn(go, 2.0f);
            const float Von = __fsub_rn(__fadd_rn(Vo, ho), mo);
            const float spko = (Von > 1.0f) ? 1.0f : 0.0f;
            const float Vop  = (Von > 1.0f) ? 0.0f : Von;
            Do[t] = __fsub_rn(Vop, Vo);
            Vo = Vop;

            const int idx = (t * B_DIM + b) * NOUT + o;
            out[idx] = spko;                               // spk_trace [T,B,O]
            out[T_DIM * B_DIM * NOUT + idx] = Vo;          // mem_trace [T,B,O]
        }
    }
}

// ---------------------------------------------------------------------------
extern "C" void kernel_launch(void* const* d_in, const int* in_sizes, int n_in,
                              void* d_out, int out_size) {
    const float* data = (const float*)d_in[0];   // [B,T,NIN]
    const float* W_h  = (const float*)d_in[1];   // [NHID,NIN]
    const float* b_h  = (const float*)d_in[2];   // [NHID]
    const float* W_o  = (const float*)d_in[3];   // [NOUT,NHID]
    const float* b_o  = (const float*)d_in[4];   // [NOUT]
    // d_in[5] = plotting (unused)

    float* I_ptr = nullptr;
    cudaGetSymbolAddress((void**)&I_ptr, g_I);   // no alloc; capture-safe

    const float scale = (float)(pow(0.1, 0.2) * tgamma(1.8));

    dim3 ggrid(B_DIM * T_DIM / BM, NHID / BN);   // (32, 4) = 128 blocks
    snn_gemm<<<ggrid, 512>>>(data, W_h, b_h, I_ptr);
    snn_hidden<<<2 * B_DIM, 256>>>(scale);
    snn_out<<<B_DIM, 512>>>(W_o, b_o, (float*)d_out, scale);
}

// round 15
// speedup vs baseline: 1.3897x; 1.1247x over previous
#include <cuda_runtime.h>
#include <cuda_bf16.h>
#include <cmath>

// Fractional LIF SNN — frozen numeric contract (validated R5-R14, rel_err 2e-6):
//   * w_sh via f32 powf (libdevice __nv_powf, matches XLA-GPU)
//   * I_h: per-output single f32 accumulator, fmaf chain, k strictly ascending
//     (fma.rn.f32x2: each 64-bit lane is exactly that chain)
//   * mem sums: ascending-s f32 fmaf chains (hidden AND output)
//   * I_o: exact sum of selected f32 weights (spk in {0,1}), rounded once
//   * elementwise recurrence ops in reference f32 order
// R15 GEMM: R8's exact per-thread inner loop (8m x 8n, plain smem — proven
// optimal mix across R9/R10/R13/R14) but tile 64x128 @ 128 threads, grid 256,
// launch_bounds(128,4): two CO-RESIDENT blocks per SM = two independent sync
// domains -> one block's warps cover the other's __syncthreads drain, and all
// 148 SMs participate (vs 128).

#define B_DIM   64
#define T_DIM   64
#define NIN     784
#define NHID    512
#define NOUT    10

__device__ float    g_I[B_DIM * T_DIM * NHID];    // 8 MB hidden currents
__device__ unsigned g_spk[B_DIM * T_DIM * 16];    // 256 KB spike bitmasks

// ---------------------------------------------------------------------------
__device__ __forceinline__ unsigned long long ffma2(unsigned long long a,
                                                    unsigned long long b,
                                                    unsigned long long c) {
    unsigned long long d;
    asm("fma.rn.f32x2 %0, %1, %2, %3;" : "=l"(d) : "l"(a), "l"(b), "l"(c));
    return d;
}
__device__ __forceinline__ unsigned long long pack2(float x) {
    unsigned long long d;
    asm("mov.b64 %0, {%1, %1};" : "=l"(d) : "f"(x));
    return d;
}

// ---------------------------------------------------------------------------
// GEMM: C[m, n] = seqchain_k( A[m,k]*W[n,k] ) + bias[n]
// M = 4096, K = 784, N = 512.  Tile 64x128x16, 128 threads (4 warps,
// 1/SMSP), 8m x 8n per thread (8 n as 4 packed f32x2), double-buffered smem,
// grid (64, 4) = 256 blocks, up to 4 blocks resident.
// Per-thread per k: 2 LDS.128 (A) + 4 LDS.64 (W) + 8 pack2 + 32 FFMA2
// (identical to R8). Bit-identical to the scalar ascending-k chain.
// ---------------------------------------------------------------------------
#define BM 64
#define BN 128
#define BK 16
#define APAD 4
#define WPAD 4

__global__ void __launch_bounds__(128, 4)
snn_gemm(const float* __restrict__ A, const float* __restrict__ W,
         const float* __restrict__ bias, float* __restrict__ C) {
    __shared__ float As[2][BK][BM + APAD];   // 8.7 KB
    __shared__ float Ws[2][BK][BN + WPAD];   // 16.9 KB

    const int tid = threadIdx.x;
    const int tx  = tid & 15;        // n-group 0..15 (8 n: 2tx + 32j)
    const int ty  = tid >> 4;        // m-group 0..7  (8 m: 8ty..8ty+7)
    const int m_blk = blockIdx.x * BM;
    const int n_blk = blockIdx.y * BN;

    // loaders: lrow = tid>>2 (0..31), kq4 = (tid&3)*4; 64B-coalesced chunks
    const int lrow = tid >> 2;
    const int kq4  = (tid & 3) * 4;

    const float* Ap = A + (size_t)(m_blk + lrow) * NIN + kq4;
    const float* Wp = W + (size_t)(n_blk + lrow) * NIN + kq4;

    float4 ra0, ra1, rw0, rw1, rw2, rw3;

    // prologue: tile 0 (A rows lrow, lrow+32; W rows lrow, +32, +64, +96)
    ra0 = *(const float4*)(Ap);
    ra1 = *(const float4*)(Ap + 32 * NIN);
    rw0 = *(const float4*)(Wp);
    rw1 = *(const float4*)(Wp + 32 * NIN);
    rw2 = *(const float4*)(Wp + 64 * NIN);
    rw3 = *(const float4*)(Wp + 96 * NIN);
    As[0][kq4 + 0][lrow] = ra0.x; As[0][kq4 + 1][lrow] = ra0.y;
    As[0][kq4 + 2][lrow] = ra0.z; As[0][kq4 + 3][lrow] = ra0.w;
    As[0][kq4 + 0][lrow + 32] = ra1.x; As[0][kq4 + 1][lrow + 32] = ra1.y;
    As[0][kq4 + 2][lrow + 32] = ra1.z; As[0][kq4 + 3][lrow + 32] = ra1.w;
    Ws[0][kq4 + 0][lrow] = rw0.x; Ws[0][kq4 + 1][lrow] = rw0.y;
    Ws[0][kq4 + 2][lrow] = rw0.z; Ws[0][kq4 + 3][lrow] = rw0.w;
    Ws[0][kq4 + 0][lrow + 32] = rw1.x; Ws[0][kq4 + 1][lrow + 32] = rw1.y;
    Ws[0][kq4 + 2][lrow + 32] = rw1.z; Ws[0][kq4 + 3][lrow + 32] = rw1.w;
    Ws[0][kq4 + 0][lrow + 64] = rw2.x; Ws[0][kq4 + 1][lrow + 64] = rw2.y;
    Ws[0][kq4 + 2][lrow + 64] = rw2.z; Ws[0][kq4 + 3][lrow + 64] = rw2.w;
    Ws[0][kq4 + 0][lrow + 96] = rw3.x; Ws[0][kq4 + 1][lrow + 96] = rw3.y;
    Ws[0][kq4 + 2][lrow + 96] = rw3.z; Ws[0][kq4 + 3][lrow + 96] = rw3.w;
    __syncthreads();

    unsigned long long acc[8][4];
#pragma unroll
    for (int m = 0; m < 8; m++)
#pragma unroll
        for (int j = 0; j < 4; j++) acc[m][j] = 0ULL;

    const int NKT = NIN / BK;   // 49
    for (int kt = 0; kt < NKT; kt++) {
        const int cur = kt & 1;
        if (kt < NKT - 1) {
            const float* Ap2 = Ap + (kt + 1) * BK;
            const float* Wp2 = Wp + (kt + 1) * BK;
            ra0 = *(const float4*)(Ap2);
            ra1 = *(const float4*)(Ap2 + 32 * NIN);
            rw0 = *(const float4*)(Wp2);
            rw1 = *(const float4*)(Wp2 + 32 * NIN);
            rw2 = *(const float4*)(Wp2 + 64 * NIN);
            rw3 = *(const float4*)(Wp2 + 96 * NIN);
        }
#pragma unroll
        for (int k = 0; k < BK; k++) {
            const float4 a01 = *(const float4*)&As[cur][k][ty * 8];
            const float4 a23 = *(const float4*)&As[cur][k][ty * 8 + 4];
            unsigned long long b2[4];
#pragma unroll
            for (int j = 0; j < 4; j++)
                b2[j] = *(const unsigned long long*)&Ws[cur][k][2 * tx + 32 * j];
            const float av[8] = {a01.x, a01.y, a01.z, a01.w,
                                 a23.x, a23.y, a23.z, a23.w};
#pragma unroll
            for (int m = 0; m < 8; m++) {
                const unsigned long long a2 = pack2(av[m]);
#pragma unroll
                for (int j = 0; j < 4; j++)
                    acc[m][j] = ffma2(a2, b2[j], acc[m][j]);
            }
        }
        if (kt < NKT - 1) {
            const int nxt = cur ^ 1;
            As[nxt][kq4 + 0][lrow] = ra0.x; As[nxt][kq4 + 1][lrow] = ra0.y;
            As[nxt][kq4 + 2][lrow] = ra0.z; As[nxt][kq4 + 3][lrow] = ra0.w;
            As[nxt][kq4 + 0][lrow + 32] = ra1.x; As[nxt][kq4 + 1][lrow + 32] = ra1.y;
            As[nxt][kq4 + 2][lrow + 32] = ra1.z; As[nxt][kq4 + 3][lrow + 32] = ra1.w;
            Ws[nxt][kq4 + 0][lrow] = rw0.x; Ws[nxt][kq4 + 1][lrow] = rw0.y;
            Ws[nxt][kq4 + 2][lrow] = rw0.z; Ws[nxt][kq4 + 3][lrow] = rw0.w;
            Ws[nxt][kq4 + 0][lrow + 32] = rw1.x; Ws[nxt][kq4 + 1][lrow + 32] = rw1.y;
            Ws[nxt][kq4 + 2][lrow + 32] = rw1.z; Ws[nxt][kq4 + 3][lrow + 32] = rw1.w;
            Ws[nxt][kq4 + 0][lrow + 64] = rw2.x; Ws[nxt][kq4 + 1][lrow + 64] = rw2.y;
            Ws[nxt][kq4 + 2][lrow + 64] = rw2.z; Ws[nxt][kq4 + 3][lrow + 64] = rw2.w;
            Ws[nxt][kq4 + 0][lrow + 96] = rw3.x; Ws[nxt][kq4 + 1][lrow + 96] = rw3.y;
            Ws[nxt][kq4 + 2][lrow + 96] = rw3.z; Ws[nxt][kq4 + 3][lrow + 96] = rw3.w;
            __syncthreads();
        }
    }

    // epilogue: add bias, store float2 (lo -> col, hi -> col+1)
#pragma unroll
    for (int m = 0; m < 8; m++) {
        const int gm = m_blk + ty * 8 + m;
#pragma unroll
        for (int j = 0; j < 4; j++) {
            const int col = n_blk + 2 * tx + 32 * j;
            const unsigned long long v = acc[m][j];
            const float lo = __uint_as_float((unsigned)(v & 0xffffffffu));
            const float hi = __uint_as_float((unsigned)(v >> 32));
            float2 o;
            o.x = __fadd_rn(lo, bias[col]);
            o.y = __fadd_rn(hi, bias[col + 1]);
            *(float2*)&C[(size_t)gm * NHID + col] = o;
        }
    }
}

// ---------------------------------------------------------------------------
// Hidden recurrence: 128 blocks (2 per batch item) x 256 threads, no barriers
// in the time loop. Spikes exported as ballot bitmasks to g_spk.
// ---------------------------------------------------------------------------
__global__ void __launch_bounds__(256, 1)
snn_hidden(float scale) {
    const int b    = blockIdx.x >> 1;
    const int half = blockIdx.x & 1;
    const int tid  = threadIdx.x;
    const int lane = tid & 31;
    const int wid  = tid >> 5;
    const int h    = half * 256 + tid;

    __shared__ float w_sh[T_DIM];
    if (tid < T_DIM) {
        // f32 powf == libdevice __nv_powf == XLA-GPU lowering (verified exact)
        const float lagf = (float)tid;
        w_sh[tid] = (tid >= 2)
                        ? (powf(lagf, 0.8f) - powf(lagf - 1.0f, 0.8f))
                        : 0.0f;
    }
    __syncthreads();

    float D[T_DIM];
    float V = 0.0f;   // VRESET
    const float* Ibase = g_I + (size_t)(b * T_DIM) * NHID + h;
    float Ibuf[4];
    Ibuf[0] = Ibase[0];
    Ibuf[1] = Ibase[NHID];
    Ibuf[2] = Ibase[2 * NHID];
    Ibuf[3] = Ibase[3 * NHID];
    const float GLc = 0.025f;

#pragma unroll
    for (int t = 0; t < T_DIM; t++) {
        const float Icur = Ibuf[t & 3];
        if (t + 4 < T_DIM)
            Ibuf[t & 3] = Ibase[(size_t)(t + 4) * NHID];

        // hidden memory: f32 sequential fmaf chain, s ascending (frozen)
        float mem = 0.0f;
#pragma unroll
        for (int s = 0; s <= t - 2; s++)
            mem = fmaf(w_sh[t - s], D[s], mem);

        // Caputo L1 update, f32 ops in reference order
        const float f  = __fadd_rn(__fmul_rn(-GLc, V), Icur);
        const float g  = __fmul_rn(scale, f);
        const float h2 = __fmul_rn(g, 2.0f);
        const float Vn = __fsub_rn(__fadd_rn(V, h2), mem);
        const float Vp = (Vn > 1.0f) ? 0.0f : Vn;
        D[t] = __fsub_rn(Vp, V);
        V = Vp;

        const unsigned msk = __ballot_sync(0xffffffffu, Vn > 1.0f);
        if (lane == 0)
            g_spk[(b * T_DIM + t) * 16 + half * 8 + wid] = msk;
    }
}

// ---------------------------------------------------------------------------
// Output layer: 64 blocks (per batch item) x 512 threads.
//   phase 2: I_o via int64 fixed-point exact sums of selected W_o entries.
//   phase 3: output recurrence on 10 threads (frozen f32 chains).
// ---------------------------------------------------------------------------
#define FIX  9007199254740992.0   // 2^53

__global__ void __launch_bounds__(512, 1)
snn_out(const float* __restrict__ Wo, const float* __restrict__ bo,
        float* __restrict__ out, float scale) {
    const int b    = blockIdx.x;
    const int tid  = threadIdx.x;
    const int lane = tid & 31;
    const int wid  = tid >> 5;

    __shared__ float     w_sh[T_DIM];
    __shared__ unsigned  msk_sh[T_DIM][16];       // 4 KB
    __shared__ long long Wo_i[NOUT][NHID];        // 40 KB
    __shared__ float     Io_sh[T_DIM][NOUT];      // 2.5 KB

    if (tid < T_DIM) {
        const float lagf = (float)tid;
        w_sh[tid] = (tid >= 2)
                        ? (powf(lagf, 0.8f) - powf(lagf - 1.0f, 0.8f))
                        : 0.0f;
    }
    for (int i = tid; i < T_DIM * 16; i += 512)
        msk_sh[i >> 4][i & 15] = g_spk[b * T_DIM * 16 + i];
    for (int i = tid; i < NOUT * NHID; i += 512)
        Wo_i[i / NHID][i % NHID] = (long long)((double)Wo[i] * FIX);
    __syncthreads();

    // ---- phase 2: 640 selective sums; warp w handles t = 4w .. 4w+3 -------
    {
        const unsigned bit = 1u << lane;
        const int t0 = wid * 4;
#pragma unroll
        for (int tt = 0; tt < 4; tt++) {
            const int t = t0 + tt;
            unsigned m[16];
#pragma unroll
            for (int j = 0; j < 16; j++) m[j] = msk_sh[t][j];
            for (int o = 0; o < NOUT; o++) {
                long long s = 0;
#pragma unroll
                for (int j = 0; j < 16; j++)
                    if (m[j] & bit) s += Wo_i[o][j * 32 + lane];
#pragma unroll
                for (int off = 16; off > 0; off >>= 1)
                    s += __shfl_xor_sync(0xffffffffu, s, off);
                if (lane == 0)
                    Io_sh[t][o] =
                        __fadd_rn((float)((double)s * (1.0 / FIX)), bo[o]);
            }
        }
    }
    __syncthreads();

    // ---- phase 3: output recurrence (10 threads) --------------------------
    if (tid < NOUT) {
        const int o = tid;
        float Do[T_DIM];
        float Vo = 0.0f;
        const float GLc = 0.025f;

#pragma unroll
        for (int t = 0; t < T_DIM; t++) {
            // output memory: f32 sequential fmaf chain, s ascending (frozen)
            float mo = 0.0f;
#pragma unroll
            for (int s = 0; s <= t - 2; s++)
                mo = fmaf(w_sh[t - s], Do[s], mo);

            const float Io  = Io_sh[t][o];
            const float fo  = __fadd_rn(__fmul_rn(-GLc, Vo), Io);
            const float go  = __fmul_rn(scale, fo);
            const float ho  = __fmul_rn(go, 2.0f);
            const float Von = __fsub_rn(__fadd_rn(Vo, ho), mo);
            const float spko = (Von > 1.0f) ? 1.0f : 0.0f;
            const float Vop  = (Von > 1.0f) ? 0.0f : Von;
            Do[t] = __fsub_rn(Vop, Vo);
            Vo = Vop;

            const int idx = (t * B_DIM + b) * NOUT + o;
            out[idx] = spko;                               // spk_trace [T,B,O]
            out[T_DIM * B_DIM * NOUT + idx] = Vo;          // mem_trace [T,B,O]
        }
    }
}

// ---------------------------------------------------------------------------
extern "C" void kernel_launch(void* const* d_in, const int* in_sizes, int n_in,
                              void* d_out, int out_size) {
    const float* data = (const float*)d_in[0];   // [B,T,NIN]
    const float* W_h  = (const float*)d_in[1];   // [NHID,NIN]
    const float* b_h  = (const float*)d_in[2];   // [NHID]
    const float* W_o  = (const float*)d_in[3];   // [NOUT,NHID]
    const float* b_o  = (const float*)d_in[4];   // [NOUT]
    // d_in[5] = plotting (unused)

    float* I_ptr = nullptr;
    cudaGetSymbolAddress((void**)&I_ptr, g_I);   // no alloc; capture-safe

    const float scale = (float)(pow(0.1, 0.2) * tgamma(1.8));

    dim3 ggrid(B_DIM * T_DIM / BM, NHID / BN);   // (64, 4) = 256 blocks
    snn_gemm<<<ggrid, 128>>>(data, W_h, b_h, I_ptr);
    snn_hidden<<<2 * B_DIM, 256>>>(scale);
    snn_out<<<B_DIM, 512>>>(W_o, b_o, (float*)d_out, scale);
}